// round 8
// baseline (speedup 1.0000x reference)
#include <cuda_runtime.h>
#include <cstdint>

#define NPTS 50000
#define DIM  128
#define W4   (DIM / 4)
#define TANCH 1024
#define KNEG 10
#define GAMMA 1.0f
#define QSCALE 20.0f

#define MA 32                 // anchors per CTA (4 per warp)
#define TN 256                // candidates per tile
#define CW 8                  // words per chunk (32 dims)
#define NCH (W4 / CW)         // 4
#define STAGES 3
#define SSEG 4
#define TILES_PER_SEG 50
#define SEG_LEN (TILES_PER_SEG * TN)    // 12800
#define N_PAD (SSEG * SEG_LEN)          // 51200
#define TOTCH (TILES_PER_SEG * NCH)     // 200

#define NSAMP 2048            // tau sample size
#define KTAU 24               // tau = 24th smallest sample key -> pool ~585
#define PCAP 320              // pool capacity per (anchor, segment)

// ---------------- static scratch ----------------
__device__ uint32_t g_BTq[2][W4][N_PAD];    // packed s8x4, transposed; pad word = 0
__device__ uint32_t g_Qrow[2][NPTS][W4];    // packed s8x4, row-major (for tau sampling)
__device__ int g_sumb2[2][N_PAD];           // per-point sum of squares (pad = huge)
__device__ int g_tau[2][TANCH];
__device__ int g_pool[2][TANCH][SSEG][PCAP];
__device__ int g_cnt[2][TANCH][SSEG];
__device__ float g_segd[2][TANCH][SSEG][KNEG];   // per-segment exact top-10 dists
__device__ int   g_segi[2][TANCH][SSEG][KNEG];
__device__ float g_partial[2 * TANCH];

// ---------------- helpers ----------------
__device__ __forceinline__ int dp4a(int acc, uint32_t a, uint32_t b) {
    int r;
    asm("dp4a.s32.s32 %0, %1, %2, %3;" : "=r"(r) : "r"(a), "r"(b), "r"(acc));
    return r;
}
__device__ __forceinline__ int quants(float v) {
    return min(127, max(-127, __float2int_rn(v * QSCALE)));
}
__device__ __forceinline__ uint32_t pack4(int q0, int q1, int q2, int q3) {
    return (uint32_t)(q0 & 0xFF) | ((uint32_t)(q1 & 0xFF) << 8) |
           ((uint32_t)(q2 & 0xFF) << 16) | ((uint32_t)(q3 & 0xFF) << 24);
}
__device__ __forceinline__ void cp_async16(uint32_t s, const void* g) {
    asm volatile("cp.async.cg.shared.global [%0], [%1], 16;\n" :: "r"(s), "l"(g));
}
__device__ __forceinline__ void cp_commit() { asm volatile("cp.async.commit_group;\n"); }
template <int N> __device__ __forceinline__ void cp_wait() {
    asm volatile("cp.async.wait_group %0;\n" :: "n"(N));
}
__device__ __forceinline__ float warp_sum(float v) {
    #pragma unroll
    for (int o = 16; o > 0; o >>= 1) v += __shfl_xor_sync(0xffffffffu, v, o);
    return v;
}
__device__ __forceinline__ int warp_min(int v) {
    #pragma unroll
    for (int o = 16; o > 0; o >>= 1) v = min(v, __shfl_xor_sync(0xffffffffu, v, o));
    return v;
}

// ---------------- kernel 1: quantize + pack + transpose + row copy + sumsq ----------------
__global__ void quant_transpose_kernel(const float* __restrict__ out1,
                                       const float* __restrict__ out2) {
    __shared__ uint32_t tile[32][33];
    const float* src = (blockIdx.z == 0) ? out1 : out2;
    uint32_t* dstT = &g_BTq[blockIdx.z][0][0];
    uint32_t* dstR = &g_Qrow[blockIdx.z][0][0];
    const int nBase = blockIdx.x * 32;
    const int tx = threadIdx.x, ty = threadIdx.y;
    #pragma unroll
    for (int j = 0; j < 32; j += 8) {
        int n = nBase + ty + j;
        uint32_t w = 0;
        int sq = 0x01000000;                 // pad: total = 0x20000000
        if (n < NPTS) {
            float4 v = *(const float4*)(src + n * DIM + 4 * tx);
            int q0 = quants(v.x), q1 = quants(v.y), q2 = quants(v.z), q3 = quants(v.w);
            w = pack4(q0, q1, q2, q3);
            sq = q0 * q0 + q1 * q1 + q2 * q2 + q3 * q3;
            dstR[n * W4 + tx] = w;
        }
        tile[ty + j][tx] = w;
        int tot = sq;
        #pragma unroll
        for (int o = 16; o > 0; o >>= 1) tot += __shfl_xor_sync(0xffffffffu, tot, o);
        if (tx == 0) g_sumb2[blockIdx.z][n] = tot;
    }
    __syncthreads();
    #pragma unroll
    for (int j = 0; j < 32; j += 8) {
        int d4 = ty + j;
        dstT[d4 * N_PAD + nBase + tx] = tile[tx][d4];
    }
}

// ---------------- kernel 2: tau threshold (24th smallest sample key) ----------------
__global__ __launch_bounds__(256)
void tau_kernel(const float* __restrict__ out1, const float* __restrict__ out2,
                const int* __restrict__ anchor1, const int* __restrict__ anchor2) {
    __shared__ uint32_t A_s[8][W4];
    const int warpId = threadIdx.x >> 5;
    const int lane = threadIdx.x & 31;
    const int g = blockIdx.x * 8 + warpId;
    const int dir = g >> 10;
    const int tt = g & 1023;
    const int bsel = (dir == 0) ? 1 : 0;
    const float* Arows = (dir == 0) ? out1 : out2;
    const int* anch = (dir == 0) ? anchor1 : anchor2;

    {
        float4 v = *(const float4*)(Arows + anch[tt] * DIM + 4 * lane);
        A_s[warpId][lane] = pack4(quants(v.x), quants(v.y), quants(v.z), quants(v.w));
    }
    __syncwarp();

    int kd[KTAU];
    #pragma unroll
    for (int k = 0; k < KTAU; ++k) kd[k] = 0x7fffffff;

    const uint32_t* A = A_s[warpId];
    for (int i = 0; i < NSAMP / 32; ++i) {
        int n = i * 32 + lane;
        const uint4* rp = (const uint4*)&g_Qrow[bsel][n][0];
        int dot = 0;
        #pragma unroll
        for (int w8 = 0; w8 < 8; ++w8) {
            uint4 b = rp[w8];
            uint4 a = *(const uint4*)&A[w8 * 4];
            dot = dp4a(dot, a.x, b.x);
            dot = dp4a(dot, a.y, b.y);
            dot = dp4a(dot, a.z, b.z);
            dot = dp4a(dot, a.w, b.w);
        }
        int key = g_sumb2[bsel][n] - 2 * dot;
        if (key < kd[KTAU - 1]) {
            #pragma unroll
            for (int j = KTAU - 1; j > 0; --j)
                kd[j] = min(kd[j], max(kd[j - 1], key));
            kd[0] = min(kd[0], key);
        }
    }

    // extract 24th smallest across warp
    int tauv = 0x7fffffff;
    #pragma unroll
    for (int r = 0; r < KTAU; ++r) {
        int gm = warp_min(kd[0]);
        if (kd[0] == gm) {
            #pragma unroll
            for (int j = 0; j < KTAU - 1; ++j) kd[j] = kd[j + 1];
            kd[KTAU - 1] = 0x7fffffff;
        }
        tauv = gm;
    }
    if (lane == 0) g_tau[dir][tt] = tauv;
}

// ---------------- kernel 3: dp4a mining (conflict-free smem), pool append ----------------
__global__ __launch_bounds__(256, 3)
void mine_kernel(const float* __restrict__ out1, const float* __restrict__ out2,
                 const int* __restrict__ anchor1, const int* __restrict__ anchor2) {
    __shared__ uint32_t Aq[W4][MA];            // 4 KB
    __shared__ uint32_t Bq[STAGES][CW][TN];    // 24 KB
    __shared__ int tau_s[MA];

    const int dir = blockIdx.z;
    const int bsel = (dir == 0) ? 1 : 0;
    const int tBase = blockIdx.x * MA;
    const int seg = blockIdx.y;
    const float* Arows = (dir == 0) ? out1 : out2;
    const int*   anch  = (dir == 0) ? anchor1 : anchor2;
    const uint32_t* BTq = &g_BTq[bsel][0][0];

    const int t = threadIdx.x;
    const int lane = t & 31;
    const int warpId = t >> 5;
    const int aB = warpId * 4;
    const int cL = lane * 4;             // low candidate group base (words)
    const int segStart = seg * SEG_LEN;

    // quantize 32 anchor rows into Aq[word][anchor]
    #pragma unroll
    for (int i = 0; i < 4; ++i) {
        int id = t + 256 * i;          // id = a*32 + w
        int a = id >> 5, w = id & 31;
        float4 v = *(const float4*)(Arows + anch[tBase + a] * DIM + 4 * w);
        Aq[w][a] = pack4(quants(v.x), quants(v.y), quants(v.z), quants(v.w));
    }
    if (t < MA) tau_s[t] = g_tau[dir][tBase + t];
    __syncthreads();

    int taus[4];
    #pragma unroll
    for (int a = 0; a < 4; ++a) taus[a] = tau_s[aB + a];
    int cnt[4] = {0, 0, 0, 0};

    auto load_chunk = [&](int s, int g) {
        uint32_t sb = (uint32_t)__cvta_generic_to_shared(&Bq[s][0][0]);
        const int n0 = segStart + (g >> 2) * TN;
        const int rowBase = (g & 3) * CW;
        #pragma unroll
        for (int i = 0; i < 2; ++i) {
            int id = t + 256 * i;              // 512 x 16B
            int r = id >> 6;
            int c4 = (id & 63) * 4;
            const uint32_t* gp = BTq + (rowBase + r) * N_PAD + n0 + c4;
            cp_async16(sb + (uint32_t)((r * TN + c4) * 4), gp);
        }
        cp_commit();
    };

    load_chunk(0, 0);
    load_chunk(1, 1);

    for (int tile = 0; tile < TILES_PER_SEG; ++tile) {
        int acc[4][8];
        #pragma unroll
        for (int a = 0; a < 4; ++a)
            #pragma unroll
            for (int j = 0; j < 8; ++j) acc[a][j] = 0;

        #pragma unroll
        for (int c = 0; c < NCH; ++c) {
            const int g = tile * NCH + c;
            if (g + 1 < TOTCH) cp_wait<1>(); else cp_wait<0>();
            __syncthreads();
            if (g + 2 < TOTCH) load_chunk((g + 2) % STAGES, g + 2);

            const uint32_t* B = &Bq[g % STAGES][0][0];
            #pragma unroll
            for (int w = 0; w < CW; ++w) {
                uint4 av = *(const uint4*)&Aq[c * CW + w][aB];
                uint4 b0 = *(const uint4*)&B[w * TN + cL];           // words lane*4..+3
                uint4 b1 = *(const uint4*)&B[w * TN + 128 + cL];     // words 128+lane*4..+3
                const uint32_t avr[4] = {av.x, av.y, av.z, av.w};
                const uint32_t bw[8] = {b0.x, b0.y, b0.z, b0.w, b1.x, b1.y, b1.z, b1.w};
                #pragma unroll
                for (int a = 0; a < 4; ++a)
                    #pragma unroll
                    for (int j = 0; j < 8; ++j)
                        acc[a][j] = dp4a(acc[a][j], avr[a], bw[j]);
            }
        }

        // finalize keys + threshold append
        const int n0 = segStart + tile * TN;
        int4 sa = *(const int4*)&g_sumb2[bsel][n0 + cL];
        int4 sb = *(const int4*)&g_sumb2[bsel][n0 + 128 + cL];
        const int s2[8] = {sa.x, sa.y, sa.z, sa.w, sb.x, sb.y, sb.z, sb.w};
        #pragma unroll
        for (int a = 0; a < 4; ++a) {
            #pragma unroll
            for (int j = 0; j < 8; ++j) {
                int key = s2[j] - 2 * acc[a][j];
                unsigned m = __ballot_sync(0xffffffffu, key < taus[a]);
                const int jo = (j < 4) ? j : (128 + j - 4);
                while (m) {
                    int src = __ffs(m) - 1; m &= m - 1;
                    if (cnt[a] < PCAP && lane == 0)
                        g_pool[dir][tBase + aB + a][seg][cnt[a]] = n0 + src * 4 + jo;
                    cnt[a]++;
                }
            }
        }
    }

    if (lane == 0) {
        #pragma unroll
        for (int a = 0; a < 4; ++a)
            g_cnt[dir][tBase + aB + a][seg] = min(cnt[a], PCAP);
    }
}

// ---------------- kernel 4: per-segment exact fp32 L1 top-10 (candidate-parallel) ----------------
__global__ __launch_bounds__(256)
void refine_seg_kernel(const float* __restrict__ out1, const float* __restrict__ out2,
                       const int* __restrict__ anchor1, const int* __restrict__ anchor2) {
    __shared__ float s_anc[8][DIM];
    const int warpId = threadIdx.x >> 5;
    const int lane = threadIdx.x & 31;
    const int gid = blockIdx.x * 8 + warpId;      // 8192 warps total
    const int seg = gid & 3;
    const int tt = (gid >> 2) & 1023;
    const int dir = gid >> 12;

    const float* Arows = (dir == 0) ? out1 : out2;
    const int* anch = (dir == 0) ? anchor1 : anchor2;
    const float* G = (dir == 0) ? out2 : out1;

    // stage self anchor row into smem
    {
        const float4* src = (const float4*)(Arows + anch[tt] * DIM);
        ((float4*)&s_anc[warpId][0])[lane] = src[lane];
    }
    __syncwarp();
    const float4* anc4 = (const float4*)&s_anc[warpId][0];

    float kd[KNEG]; int ki[KNEG];
    #pragma unroll
    for (int k = 0; k < KNEG; ++k) { kd[k] = 3.0e38f; ki[k] = 0x7fffffff; }

    const int cnt = g_cnt[dir][tt][seg];
    const int* pool = &g_pool[dir][tt][seg][0];
    for (int base = 0; base < cnt; base += 32) {
        const int k = base + lane;
        int idx = -1;
        float dsum = 3.0e38f;
        if (k < cnt) {
            idx = min(pool[k], NPTS - 1);
            const float4* nr = (const float4*)(G + idx * DIM);
            dsum = 0.0f;
            #pragma unroll 8
            for (int j = 0; j < 32; ++j) {
                float4 b = nr[j];
                float4 a = anc4[j];
                dsum += fabsf(a.x - b.x) + fabsf(a.y - b.y) +
                        fabsf(a.z - b.z) + fabsf(a.w - b.w);
            }
        }
        float thr = __shfl_sync(0xffffffffu, kd[KNEG - 1], 0);
        int   thi = __shfl_sync(0xffffffffu, ki[KNEG - 1], 0);
        bool candp = (idx >= 0) && (dsum < thr || (dsum == thr && idx < thi));
        unsigned m = __ballot_sync(0xffffffffu, candp);
        while (m) {
            int src = __ffs(m) - 1; m &= m - 1;
            float d = __shfl_sync(0xffffffffu, dsum, src);
            int  ix = __shfl_sync(0xffffffffu, idx, src);
            if (lane == 0) {
                bool better = (d < kd[KNEG - 1]) ||
                              (d == kd[KNEG - 1] && ix < ki[KNEG - 1]);
                if (better) {
                    int pos = KNEG - 1;
                    #pragma unroll
                    for (int q = KNEG - 2; q >= 0; --q)
                        if (kd[q] > d || (kd[q] == d && ki[q] > ix)) pos = q;
                    #pragma unroll
                    for (int q = KNEG - 1; q > 0; --q)
                        if (q > pos) { kd[q] = kd[q - 1]; ki[q] = ki[q - 1]; }
                    kd[pos] = d; ki[pos] = ix;
                }
            }
        }
    }
    if (lane == 0) {
        #pragma unroll
        for (int k = 0; k < KNEG; ++k) {
            g_segd[dir][tt][seg][k] = kd[k];
            g_segi[dir][tt][seg][k] = ki[k];
        }
    }
}

// ---------------- kernel 5: merge segments + loss (no gathers) ----------------
__global__ __launch_bounds__(256)
void merge_loss_kernel(const float* __restrict__ out1, const float* __restrict__ out2,
                       const int* __restrict__ anchor1, const int* __restrict__ anchor2) {
    const int warpId = threadIdx.x >> 5;
    const int lane = threadIdx.x & 31;
    const int g = blockIdx.x * 8 + warpId;
    const int dir = g >> 10;
    const int tt = g & 1023;

    const float* r1 = out1 + anchor1[tt] * DIM;
    const float* r2 = out2 + anchor2[tt] * DIM;
    float A = 0.0f;
    #pragma unroll
    for (int j = 0; j < 4; ++j)
        A += fabsf(r1[lane + 32 * j] - r2[lane + 32 * j]);
    A = warp_sum(A);
    const float Dm = A + GAMMA;

    if (lane == 0) {
        float kd[KNEG]; int ki[KNEG];
        #pragma unroll
        for (int k = 0; k < KNEG; ++k) { kd[k] = 3.0e38f; ki[k] = 0x7fffffff; }
        for (int seg = 0; seg < SSEG; ++seg) {
            #pragma unroll
            for (int k = 0; k < KNEG; ++k) {
                float d = g_segd[dir][tt][seg][k];
                int  ix = g_segi[dir][tt][seg][k];
                bool better = (d < kd[KNEG - 1]) ||
                              (d == kd[KNEG - 1] && ix < ki[KNEG - 1]);
                if (better) {
                    int pos = KNEG - 1;
                    #pragma unroll
                    for (int q = KNEG - 2; q >= 0; --q)
                        if (kd[q] > d || (kd[q] == d && ki[q] > ix)) pos = q;
                    #pragma unroll
                    for (int q = KNEG - 1; q > 0; --q)
                        if (q > pos) { kd[q] = kd[q - 1]; ki[q] = ki[q - 1]; }
                    kd[pos] = d; ki[pos] = ix;
                }
            }
        }
        float lsum = 0.0f;
        #pragma unroll
        for (int k = 0; k < KNEG; ++k) lsum += fmaxf(Dm - kd[k], 0.0f);
        g_partial[g] = lsum;
    }
}

// ---------------- kernel 6: deterministic reduction ----------------
__global__ void reduce_kernel(float* __restrict__ out) {
    __shared__ float sh[1024];
    int t = threadIdx.x;
    sh[t] = g_partial[t] + g_partial[t + 1024];
    __syncthreads();
    #pragma unroll
    for (int s = 512; s > 0; s >>= 1) {
        if (t < s) sh[t] += sh[t + s];
        __syncthreads();
    }
    if (t == 0) out[0] = sh[0] * (1.0f / (float)(TANCH * KNEG));
}

// ---------------- launch ----------------
extern "C" void kernel_launch(void* const* d_in, const int* in_sizes, int n_in,
                              void* d_out, int out_size) {
    const float* out1 = (const float*)d_in[0];
    const float* out2 = (const float*)d_in[1];
    const int* anchor1 = (const int*)d_in[2];
    const int* anchor2 = (const int*)d_in[3];
    float* out = (float*)d_out;

    quant_transpose_kernel<<<dim3(N_PAD / 32, 1, 2), dim3(32, 8)>>>(out1, out2);

    tau_kernel<<<2 * TANCH / 8, 256>>>(out1, out2, anchor1, anchor2);

    mine_kernel<<<dim3(TANCH / MA, SSEG, 2), 256>>>(out1, out2, anchor1, anchor2);

    refine_seg_kernel<<<2 * TANCH * SSEG / 8, 256>>>(out1, out2, anchor1, anchor2);

    merge_loss_kernel<<<2 * TANCH / 8, 256>>>(out1, out2, anchor1, anchor2);

    reduce_kernel<<<1, 1024>>>(out);
}

// round 9
// speedup vs baseline: 1.0956x; 1.0956x over previous
#include <cuda_runtime.h>
#include <cstdint>

#define NPTS 50000
#define DIM  128
#define W4   (DIM / 4)
#define TANCH 1024
#define KNEG 10
#define GAMMA 1.0f
#define QSCALE 20.0f

#define MA 32                 // anchors per CTA (4 per warp)
#define TN 256                // candidates per tile
#define CW 8                  // words per chunk (32 dims)
#define NCH (W4 / CW)         // 4
#define STAGES 3
#define SSEG 4
#define TILES_PER_SEG 50
#define SEG_LEN (TILES_PER_SEG * TN)    // 12800
#define N_PAD (SSEG * SEG_LEN)          // 51200
#define TOTCH (TILES_PER_SEG * NCH)     // 200

#define NSAMP 2048            // tau sample size
#define KTAU 24               // tau = 24th smallest sample key -> pool ~585
#define PCAP 320              // pool capacity per (anchor, segment)

// ---------------- static scratch ----------------
__device__ uint32_t g_BTq[2][W4][N_PAD];    // packed s8x4, transposed; pad word = 0
__device__ uint32_t g_Qrow[2][NPTS][W4];    // packed s8x4, row-major (for tau sampling)
__device__ int g_sumb2[2][N_PAD];           // per-point sum of squares (pad = huge)
__device__ int g_tau[2][TANCH];
__device__ int g_pool[2][TANCH][SSEG][PCAP];
__device__ int g_cnt[2][TANCH][SSEG];
__device__ float g_segd[2][TANCH][SSEG][KNEG];   // per-segment exact top-10 dists
__device__ int   g_segi[2][TANCH][SSEG][KNEG];
__device__ float g_partial[2 * TANCH];

// ---------------- helpers ----------------
__device__ __forceinline__ int dp4a(int acc, uint32_t a, uint32_t b) {
    int r;
    asm("dp4a.s32.s32 %0, %1, %2, %3;" : "=r"(r) : "r"(a), "r"(b), "r"(acc));
    return r;
}
__device__ __forceinline__ int quants(float v) {
    return min(127, max(-127, __float2int_rn(v * QSCALE)));
}
__device__ __forceinline__ uint32_t pack4(int q0, int q1, int q2, int q3) {
    return (uint32_t)(q0 & 0xFF) | ((uint32_t)(q1 & 0xFF) << 8) |
           ((uint32_t)(q2 & 0xFF) << 16) | ((uint32_t)(q3 & 0xFF) << 24);
}
__device__ __forceinline__ void cp_async16(uint32_t s, const void* g) {
    asm volatile("cp.async.cg.shared.global [%0], [%1], 16;\n" :: "r"(s), "l"(g));
}
__device__ __forceinline__ void cp_commit() { asm volatile("cp.async.commit_group;\n"); }
template <int N> __device__ __forceinline__ void cp_wait() {
    asm volatile("cp.async.wait_group %0;\n" :: "n"(N));
}
__device__ __forceinline__ float warp_sum(float v) {
    #pragma unroll
    for (int o = 16; o > 0; o >>= 1) v += __shfl_xor_sync(0xffffffffu, v, o);
    return v;
}
__device__ __forceinline__ int warp_min(int v) {
    #pragma unroll
    for (int o = 16; o > 0; o >>= 1) v = min(v, __shfl_xor_sync(0xffffffffu, v, o));
    return v;
}

// ---------------- kernel 1: quantize + pack + transpose + row copy + sumsq ----------------
__global__ void quant_transpose_kernel(const float* __restrict__ out1,
                                       const float* __restrict__ out2) {
    __shared__ uint32_t tile[32][33];
    const float* src = (blockIdx.z == 0) ? out1 : out2;
    uint32_t* dstT = &g_BTq[blockIdx.z][0][0];
    uint32_t* dstR = &g_Qrow[blockIdx.z][0][0];
    const int nBase = blockIdx.x * 32;
    const int tx = threadIdx.x, ty = threadIdx.y;
    #pragma unroll
    for (int j = 0; j < 32; j += 8) {
        int n = nBase + ty + j;
        uint32_t w = 0;
        int sq = 0x01000000;                 // pad: total = 0x20000000
        if (n < NPTS) {
            float4 v = *(const float4*)(src + n * DIM + 4 * tx);
            int q0 = quants(v.x), q1 = quants(v.y), q2 = quants(v.z), q3 = quants(v.w);
            w = pack4(q0, q1, q2, q3);
            sq = q0 * q0 + q1 * q1 + q2 * q2 + q3 * q3;
            dstR[n * W4 + tx] = w;
        }
        tile[ty + j][tx] = w;
        int tot = sq;
        #pragma unroll
        for (int o = 16; o > 0; o >>= 1) tot += __shfl_xor_sync(0xffffffffu, tot, o);
        if (tx == 0) g_sumb2[blockIdx.z][n] = tot;
    }
    __syncthreads();
    #pragma unroll
    for (int j = 0; j < 32; j += 8) {
        int d4 = ty + j;
        dstT[d4 * N_PAD + nBase + tx] = tile[tx][d4];
    }
}

// ---------------- kernel 2: tau threshold (24th smallest sample key) ----------------
__global__ __launch_bounds__(256)
void tau_kernel(const float* __restrict__ out1, const float* __restrict__ out2,
                const int* __restrict__ anchor1, const int* __restrict__ anchor2) {
    __shared__ uint32_t A_s[8][W4];
    const int warpId = threadIdx.x >> 5;
    const int lane = threadIdx.x & 31;
    const int g = blockIdx.x * 8 + warpId;
    const int dir = g >> 10;
    const int tt = g & 1023;
    const int bsel = (dir == 0) ? 1 : 0;
    const float* Arows = (dir == 0) ? out1 : out2;
    const int* anch = (dir == 0) ? anchor1 : anchor2;

    {
        float4 v = *(const float4*)(Arows + anch[tt] * DIM + 4 * lane);
        A_s[warpId][lane] = pack4(quants(v.x), quants(v.y), quants(v.z), quants(v.w));
    }
    __syncwarp();

    int kd[KTAU];
    #pragma unroll
    for (int k = 0; k < KTAU; ++k) kd[k] = 0x7fffffff;

    const uint32_t* A = A_s[warpId];
    for (int i = 0; i < NSAMP / 32; ++i) {
        int n = i * 32 + lane;
        const uint4* rp = (const uint4*)&g_Qrow[bsel][n][0];
        int dot = 0;
        #pragma unroll
        for (int w8 = 0; w8 < 8; ++w8) {
            uint4 b = rp[w8];
            uint4 a = *(const uint4*)&A[w8 * 4];
            dot = dp4a(dot, a.x, b.x);
            dot = dp4a(dot, a.y, b.y);
            dot = dp4a(dot, a.z, b.z);
            dot = dp4a(dot, a.w, b.w);
        }
        int key = g_sumb2[bsel][n] - 2 * dot;
        if (key < kd[KTAU - 1]) {
            #pragma unroll
            for (int j = KTAU - 1; j > 0; --j)
                kd[j] = min(kd[j], max(kd[j - 1], key));
            kd[0] = min(kd[0], key);
        }
    }

    // extract 24th smallest across warp
    int tauv = 0x7fffffff;
    #pragma unroll
    for (int r = 0; r < KTAU; ++r) {
        int gm = warp_min(kd[0]);
        if (kd[0] == gm) {
            #pragma unroll
            for (int j = 0; j < KTAU - 1; ++j) kd[j] = kd[j + 1];
            kd[KTAU - 1] = 0x7fffffff;
        }
        tauv = gm;
    }
    if (lane == 0) g_tau[dir][tt] = tauv;
}

// ---------------- kernel 3: dp4a mining (conflict-free smem), pool append ----------------
__global__ __launch_bounds__(256, 3)
void mine_kernel(const float* __restrict__ out1, const float* __restrict__ out2,
                 const int* __restrict__ anchor1, const int* __restrict__ anchor2) {
    __shared__ uint32_t Aq[W4][MA];            // 4 KB
    __shared__ uint32_t Bq[STAGES][CW][TN];    // 24 KB
    __shared__ int tau_s[MA];

    const int dir = blockIdx.z;
    const int bsel = (dir == 0) ? 1 : 0;
    const int tBase = blockIdx.x * MA;
    const int seg = blockIdx.y;
    const float* Arows = (dir == 0) ? out1 : out2;
    const int*   anch  = (dir == 0) ? anchor1 : anchor2;
    const uint32_t* BTq = &g_BTq[bsel][0][0];

    const int t = threadIdx.x;
    const int lane = t & 31;
    const int warpId = t >> 5;
    const int aB = warpId * 4;
    const int cL = lane * 4;             // low candidate group base (words)
    const int segStart = seg * SEG_LEN;

    // quantize 32 anchor rows into Aq[word][anchor]
    #pragma unroll
    for (int i = 0; i < 4; ++i) {
        int id = t + 256 * i;          // id = a*32 + w
        int a = id >> 5, w = id & 31;
        float4 v = *(const float4*)(Arows + anch[tBase + a] * DIM + 4 * w);
        Aq[w][a] = pack4(quants(v.x), quants(v.y), quants(v.z), quants(v.w));
    }
    if (t < MA) tau_s[t] = g_tau[dir][tBase + t];
    __syncthreads();

    int taus[4];
    #pragma unroll
    for (int a = 0; a < 4; ++a) taus[a] = tau_s[aB + a];
    int cnt[4] = {0, 0, 0, 0};

    auto load_chunk = [&](int s, int g) {
        uint32_t sb = (uint32_t)__cvta_generic_to_shared(&Bq[s][0][0]);
        const int n0 = segStart + (g >> 2) * TN;
        const int rowBase = (g & 3) * CW;
        #pragma unroll
        for (int i = 0; i < 2; ++i) {
            int id = t + 256 * i;              // 512 x 16B
            int r = id >> 6;
            int c4 = (id & 63) * 4;
            const uint32_t* gp = BTq + (rowBase + r) * N_PAD + n0 + c4;
            cp_async16(sb + (uint32_t)((r * TN + c4) * 4), gp);
        }
        cp_commit();
    };

    load_chunk(0, 0);
    load_chunk(1, 1);

    for (int tile = 0; tile < TILES_PER_SEG; ++tile) {
        int acc[4][8];
        #pragma unroll
        for (int a = 0; a < 4; ++a)
            #pragma unroll
            for (int j = 0; j < 8; ++j) acc[a][j] = 0;

        #pragma unroll
        for (int c = 0; c < NCH; ++c) {
            const int g = tile * NCH + c;
            if (g + 1 < TOTCH) cp_wait<1>(); else cp_wait<0>();
            __syncthreads();
            if (g + 2 < TOTCH) load_chunk((g + 2) % STAGES, g + 2);

            const uint32_t* B = &Bq[g % STAGES][0][0];
            #pragma unroll
            for (int w = 0; w < CW; ++w) {
                uint4 av = *(const uint4*)&Aq[c * CW + w][aB];
                uint4 b0 = *(const uint4*)&B[w * TN + cL];           // words lane*4..+3
                uint4 b1 = *(const uint4*)&B[w * TN + 128 + cL];     // words 128+lane*4..+3
                const uint32_t avr[4] = {av.x, av.y, av.z, av.w};
                const uint32_t bw[8] = {b0.x, b0.y, b0.z, b0.w, b1.x, b1.y, b1.z, b1.w};
                #pragma unroll
                for (int a = 0; a < 4; ++a)
                    #pragma unroll
                    for (int j = 0; j < 8; ++j)
                        acc[a][j] = dp4a(acc[a][j], avr[a], bw[j]);
            }
        }

        // finalize keys + threshold append
        const int n0 = segStart + tile * TN;
        int4 sa = *(const int4*)&g_sumb2[bsel][n0 + cL];
        int4 sb = *(const int4*)&g_sumb2[bsel][n0 + 128 + cL];
        const int s2[8] = {sa.x, sa.y, sa.z, sa.w, sb.x, sb.y, sb.z, sb.w};
        #pragma unroll
        for (int a = 0; a < 4; ++a) {
            #pragma unroll
            for (int j = 0; j < 8; ++j) {
                int key = s2[j] - 2 * acc[a][j];
                unsigned m = __ballot_sync(0xffffffffu, key < taus[a]);
                const int jo = (j < 4) ? j : (128 + j - 4);
                while (m) {
                    int src = __ffs(m) - 1; m &= m - 1;
                    if (cnt[a] < PCAP && lane == 0)
                        g_pool[dir][tBase + aB + a][seg][cnt[a]] = n0 + src * 4 + jo;
                    cnt[a]++;
                }
            }
        }
    }

    if (lane == 0) {
        #pragma unroll
        for (int a = 0; a < 4; ++a)
            g_cnt[dir][tBase + aB + a][seg] = min(cnt[a], PCAP);
    }
}

// ---------------- kernel 4: per-segment exact fp32 L1 top-10 (subwarp-coalesced) ----------------
__global__ __launch_bounds__(256)
void refine_seg_kernel(const float* __restrict__ out1, const float* __restrict__ out2,
                       const int* __restrict__ anchor1, const int* __restrict__ anchor2) {
    __shared__ float s_anc[8][DIM];
    const int warpId = threadIdx.x >> 5;
    const int lane = threadIdx.x & 31;
    const int sw = lane >> 3;          // subwarp 0..3 (one candidate each)
    const int sl = lane & 7;           // lane within subwarp
    const int gid = blockIdx.x * 8 + warpId;      // 8192 warps total
    const int seg = gid & 3;
    const int tt = (gid >> 2) & 1023;
    const int dir = gid >> 12;

    const float* Arows = (dir == 0) ? out1 : out2;
    const int* anch = (dir == 0) ? anchor1 : anchor2;
    const float* G = (dir == 0) ? out2 : out1;

    // stage self anchor row into smem
    {
        const float4* src = (const float4*)(Arows + anch[tt] * DIM);
        ((float4*)&s_anc[warpId][0])[lane] = src[lane];
    }
    __syncwarp();
    const float4* anc4 = (const float4*)&s_anc[warpId][0];

    float kd[KNEG]; int ki[KNEG];
    #pragma unroll
    for (int k = 0; k < KNEG; ++k) { kd[k] = 3.0e38f; ki[k] = 0x7fffffff; }

    const int cnt = g_cnt[dir][tt][seg];
    const int* pool = &g_pool[dir][tt][seg][0];
    for (int base = 0; base < cnt; base += 4) {
        const int k = base + sw;       // all 8 lanes of a subwarp share k
        int idx = -1;
        float dsum = 3.0e38f;
        if (k < cnt) {
            idx = min(pool[k], NPTS - 1);
            const float4* nr = (const float4*)(G + idx * DIM);
            float p = 0.0f;
            #pragma unroll
            for (int j = 0; j < 4; ++j) {
                float4 b = nr[sl + 8 * j];       // 8 lanes cover 128B contiguous
                float4 a = anc4[sl + 8 * j];
                p += fabsf(a.x - b.x) + fabsf(a.y - b.y) +
                     fabsf(a.z - b.z) + fabsf(a.w - b.w);
            }
            // reduce within subwarp (8 lanes)
            p += __shfl_xor_sync(0xffffffffu, p, 4);
            p += __shfl_xor_sync(0xffffffffu, p, 2);
            p += __shfl_xor_sync(0xffffffffu, p, 1);
            dsum = p;
        } else {
            // keep shfl participation consistent
            float p = 0.0f;
            p += __shfl_xor_sync(0xffffffffu, p, 4);
            p += __shfl_xor_sync(0xffffffffu, p, 2);
            p += __shfl_xor_sync(0xffffffffu, p, 1);
        }
        float thr = __shfl_sync(0xffffffffu, kd[KNEG - 1], 0);
        int   thi = __shfl_sync(0xffffffffu, ki[KNEG - 1], 0);
        bool candp = (sl == 0) && (idx >= 0) &&
                     (dsum < thr || (dsum == thr && idx < thi));
        unsigned m = __ballot_sync(0xffffffffu, candp);
        while (m) {
            int src = __ffs(m) - 1; m &= m - 1;
            float d = __shfl_sync(0xffffffffu, dsum, src);
            int  ix = __shfl_sync(0xffffffffu, idx, src);
            if (lane == 0) {
                bool better = (d < kd[KNEG - 1]) ||
                              (d == kd[KNEG - 1] && ix < ki[KNEG - 1]);
                if (better) {
                    int pos = KNEG - 1;
                    #pragma unroll
                    for (int q = KNEG - 2; q >= 0; --q)
                        if (kd[q] > d || (kd[q] == d && ki[q] > ix)) pos = q;
                    #pragma unroll
                    for (int q = KNEG - 1; q > 0; --q)
                        if (q > pos) { kd[q] = kd[q - 1]; ki[q] = ki[q - 1]; }
                    kd[pos] = d; ki[pos] = ix;
                }
            }
        }
    }
    if (lane == 0) {
        #pragma unroll
        for (int k = 0; k < KNEG; ++k) {
            g_segd[dir][tt][seg][k] = kd[k];
            g_segi[dir][tt][seg][k] = ki[k];
        }
    }
}

// ---------------- kernel 5: merge segments + loss (no gathers) ----------------
__global__ __launch_bounds__(256)
void merge_loss_kernel(const float* __restrict__ out1, const float* __restrict__ out2,
                       const int* __restrict__ anchor1, const int* __restrict__ anchor2) {
    const int warpId = threadIdx.x >> 5;
    const int lane = threadIdx.x & 31;
    const int g = blockIdx.x * 8 + warpId;
    const int dir = g >> 10;
    const int tt = g & 1023;

    const float* r1 = out1 + anchor1[tt] * DIM;
    const float* r2 = out2 + anchor2[tt] * DIM;
    float A = 0.0f;
    #pragma unroll
    for (int j = 0; j < 4; ++j)
        A += fabsf(r1[lane + 32 * j] - r2[lane + 32 * j]);
    A = warp_sum(A);
    const float Dm = A + GAMMA;

    if (lane == 0) {
        float kd[KNEG]; int ki[KNEG];
        #pragma unroll
        for (int k = 0; k < KNEG; ++k) { kd[k] = 3.0e38f; ki[k] = 0x7fffffff; }
        for (int seg = 0; seg < SSEG; ++seg) {
            #pragma unroll
            for (int k = 0; k < KNEG; ++k) {
                float d = g_segd[dir][tt][seg][k];
                int  ix = g_segi[dir][tt][seg][k];
                bool better = (d < kd[KNEG - 1]) ||
                              (d == kd[KNEG - 1] && ix < ki[KNEG - 1]);
                if (better) {
                    int pos = KNEG - 1;
                    #pragma unroll
                    for (int q = KNEG - 2; q >= 0; --q)
                        if (kd[q] > d || (kd[q] == d && ki[q] > ix)) pos = q;
                    #pragma unroll
                    for (int q = KNEG - 1; q > 0; --q)
                        if (q > pos) { kd[q] = kd[q - 1]; ki[q] = ki[q - 1]; }
                    kd[pos] = d; ki[pos] = ix;
                }
            }
        }
        float lsum = 0.0f;
        #pragma unroll
        for (int k = 0; k < KNEG; ++k) lsum += fmaxf(Dm - kd[k], 0.0f);
        g_partial[g] = lsum;
    }
}

// ---------------- kernel 6: deterministic reduction ----------------
__global__ void reduce_kernel(float* __restrict__ out) {
    __shared__ float sh[1024];
    int t = threadIdx.x;
    sh[t] = g_partial[t] + g_partial[t + 1024];
    __syncthreads();
    #pragma unroll
    for (int s = 512; s > 0; s >>= 1) {
        if (t < s) sh[t] += sh[t + s];
        __syncthreads();
    }
    if (t == 0) out[0] = sh[0] * (1.0f / (float)(TANCH * KNEG));
}

// ---------------- launch ----------------
extern "C" void kernel_launch(void* const* d_in, const int* in_sizes, int n_in,
                              void* d_out, int out_size) {
    const float* out1 = (const float*)d_in[0];
    const float* out2 = (const float*)d_in[1];
    const int* anchor1 = (const int*)d_in[2];
    const int* anchor2 = (const int*)d_in[3];
    float* out = (float*)d_out;

    quant_transpose_kernel<<<dim3(N_PAD / 32, 1, 2), dim3(32, 8)>>>(out1, out2);

    tau_kernel<<<2 * TANCH / 8, 256>>>(out1, out2, anchor1, anchor2);

    mine_kernel<<<dim3(TANCH / MA, SSEG, 2), 256>>>(out1, out2, anchor1, anchor2);

    refine_seg_kernel<<<2 * TANCH * SSEG / 8, 256>>>(out1, out2, anchor1, anchor2);

    merge_loss_kernel<<<2 * TANCH / 8, 256>>>(out1, out2, anchor1, anchor2);

    reduce_kernel<<<1, 1024>>>(out);
}

// round 10
// speedup vs baseline: 1.1892x; 1.0854x over previous
#include <cuda_runtime.h>
#include <cstdint>

#define NPTS 50000
#define DIM  128
#define W4   (DIM / 4)
#define TANCH 1024
#define KNEG 10
#define GAMMA 1.0f
#define QSCALE 20.0f

#define NSEG 8
#define TILE_N 128
#define TILES_PER_SEG 49
#define SEG_LEN (TILES_PER_SEG * TILE_N)   // 6272
#define N_PAD (NSEG * SEG_LEN)             // 50176

#define NSAMP 2048
#define KTAU 24               // tau = 24th smallest sample key -> pool ~585 total
#define PCAP 192              // pool capacity per (anchor, segment)

#define BPAD 36               // padded row stride (words) for smem tiles

// ---------------- static scratch ----------------
__device__ uint32_t g_Qrow[2][N_PAD][W4];   // packed s8x4 row-major (pad rows = 0)
__device__ int g_sumb2[2][N_PAD];           // per-point sum of squares (pad = huge)
__device__ int g_tau[2][TANCH];
__device__ int g_pool[2][TANCH][NSEG][PCAP];
__device__ int g_cnt[2][TANCH][NSEG];
__device__ float g_segd[2][TANCH][NSEG][KNEG];
__device__ int   g_segi[2][TANCH][NSEG][KNEG];
__device__ float g_partial[2 * TANCH];

// ---------------- helpers ----------------
__device__ __forceinline__ int dp4a(int acc, uint32_t a, uint32_t b) {
    int r;
    asm("dp4a.s32.s32 %0, %1, %2, %3;" : "=r"(r) : "r"(a), "r"(b), "r"(acc));
    return r;
}
__device__ __forceinline__ void mma_s8(int* c, const uint32_t* a, uint32_t b0, uint32_t b1) {
    asm volatile(
        "mma.sync.aligned.m16n8k32.row.col.s32.s8.s8.s32 "
        "{%0,%1,%2,%3},{%4,%5,%6,%7},{%8,%9},{%0,%1,%2,%3};"
        : "+r"(c[0]), "+r"(c[1]), "+r"(c[2]), "+r"(c[3])
        : "r"(a[0]), "r"(a[1]), "r"(a[2]), "r"(a[3]), "r"(b0), "r"(b1));
}
__device__ __forceinline__ int quants(float v) {
    return min(127, max(-127, __float2int_rn(v * QSCALE)));
}
__device__ __forceinline__ uint32_t pack4(int q0, int q1, int q2, int q3) {
    return (uint32_t)(q0 & 0xFF) | ((uint32_t)(q1 & 0xFF) << 8) |
           ((uint32_t)(q2 & 0xFF) << 16) | ((uint32_t)(q3 & 0xFF) << 24);
}
__device__ __forceinline__ void cp_async16(uint32_t s, const void* g) {
    asm volatile("cp.async.cg.shared.global [%0], [%1], 16;\n" :: "r"(s), "l"(g));
}
__device__ __forceinline__ void cp_commit() { asm volatile("cp.async.commit_group;\n"); }
template <int N> __device__ __forceinline__ void cp_wait() {
    asm volatile("cp.async.wait_group %0;\n" :: "n"(N));
}
__device__ __forceinline__ float warp_sum(float v) {
    #pragma unroll
    for (int o = 16; o > 0; o >>= 1) v += __shfl_xor_sync(0xffffffffu, v, o);
    return v;
}
__device__ __forceinline__ int warp_min(int v) {
    #pragma unroll
    for (int o = 16; o > 0; o >>= 1) v = min(v, __shfl_xor_sync(0xffffffffu, v, o));
    return v;
}

// ---------------- kernel 1: quantize + pack (row-major) + sumsq ----------------
__global__ void quant_kernel(const float* __restrict__ out1,
                             const float* __restrict__ out2) {
    const float* src = (blockIdx.z == 0) ? out1 : out2;
    const int warpId = threadIdx.x >> 5;
    const int lane = threadIdx.x & 31;
    const int rowBase = blockIdx.x * 64 + warpId * 8;
    #pragma unroll
    for (int r = 0; r < 8; ++r) {
        int n = rowBase + r;
        if (n < NPTS) {
            float4 v = *(const float4*)(src + n * DIM + 4 * lane);
            int q0 = quants(v.x), q1 = quants(v.y), q2 = quants(v.z), q3 = quants(v.w);
            g_Qrow[blockIdx.z][n][lane] = pack4(q0, q1, q2, q3);
            int sq = q0 * q0 + q1 * q1 + q2 * q2 + q3 * q3;
            sq = warp_sum(__int_as_float(0)) == 0.0f ? sq : sq; // no-op keep
            int tot = sq;
            #pragma unroll
            for (int o = 16; o > 0; o >>= 1) tot += __shfl_xor_sync(0xffffffffu, tot, o);
            if (lane == 0) g_sumb2[blockIdx.z][n] = tot;
        } else {
            g_Qrow[blockIdx.z][n][lane] = 0;
            if (lane == 0) g_sumb2[blockIdx.z][n] = 0x20000000;
        }
    }
}

// ---------------- kernel 2: tau threshold (24th smallest sample key) ----------------
__global__ __launch_bounds__(256)
void tau_kernel(const float* __restrict__ out1, const float* __restrict__ out2,
                const int* __restrict__ anchor1, const int* __restrict__ anchor2) {
    __shared__ uint32_t A_s[8][W4];
    const int warpId = threadIdx.x >> 5;
    const int lane = threadIdx.x & 31;
    const int g = blockIdx.x * 8 + warpId;
    const int dir = g >> 10;
    const int tt = g & 1023;
    const int bsel = (dir == 0) ? 1 : 0;
    const float* Arows = (dir == 0) ? out1 : out2;
    const int* anch = (dir == 0) ? anchor1 : anchor2;

    {
        float4 v = *(const float4*)(Arows + anch[tt] * DIM + 4 * lane);
        A_s[warpId][lane] = pack4(quants(v.x), quants(v.y), quants(v.z), quants(v.w));
    }
    __syncwarp();

    int kd[KTAU];
    #pragma unroll
    for (int k = 0; k < KTAU; ++k) kd[k] = 0x7fffffff;

    const uint32_t* A = A_s[warpId];
    for (int i = 0; i < NSAMP / 32; ++i) {
        int n = i * 32 + lane;
        const uint4* rp = (const uint4*)&g_Qrow[bsel][n][0];
        int dot = 0;
        #pragma unroll
        for (int w8 = 0; w8 < 8; ++w8) {
            uint4 b = rp[w8];
            uint4 a = *(const uint4*)&A[w8 * 4];
            dot = dp4a(dot, a.x, b.x);
            dot = dp4a(dot, a.y, b.y);
            dot = dp4a(dot, a.z, b.z);
            dot = dp4a(dot, a.w, b.w);
        }
        int key = g_sumb2[bsel][n] - 2 * dot;
        if (key < kd[KTAU - 1]) {
            #pragma unroll
            for (int j = KTAU - 1; j > 0; --j)
                kd[j] = min(kd[j], max(kd[j - 1], key));
            kd[0] = min(kd[0], key);
        }
    }

    int tauv = 0x7fffffff;
    #pragma unroll
    for (int r = 0; r < KTAU; ++r) {
        int gm = warp_min(kd[0]);
        if (kd[0] == gm) {
            #pragma unroll
            for (int j = 0; j < KTAU - 1; ++j) kd[j] = kd[j + 1];
            kd[KTAU - 1] = 0x7fffffff;
        }
        tauv = gm;
    }
    if (lane == 0) g_tau[dir][tt] = tauv;
}

// ---------------- kernel 3: IMMA mining (m16n8k32 s8), pool append ----------------
__global__ __launch_bounds__(256)
void mine_mma_kernel(const float* __restrict__ out1, const float* __restrict__ out2,
                     const int* __restrict__ anchor1, const int* __restrict__ anchor2) {
    __shared__ uint32_t sA[32][BPAD];              // 4.6 KB anchors (32 x 128 s8)
    __shared__ uint32_t sB[2][TILE_N][BPAD];       // 36.9 KB candidate tiles
    __shared__ int tau_s[32];
    __shared__ int scnt[32];

    const int dir = blockIdx.z;
    const int bsel = (dir == 0) ? 1 : 0;
    const int seg = blockIdx.y;
    const int tBase = blockIdx.x * 32;
    const float* Arows = (dir == 0) ? out1 : out2;
    const int*   anch  = (dir == 0) ? anchor1 : anchor2;

    const int tid = threadIdx.x;
    const int warpId = tid >> 5;
    const int lane = tid & 31;
    const int gid = lane >> 2;          // 0..7
    const int tig = lane & 3;           // 0..3
    const int segStart = seg * SEG_LEN;

    // quantize 32 anchor rows into sA[m][word]
    #pragma unroll
    for (int i = 0; i < 4; ++i) {
        int id = tid + 256 * i;             // a*32 + w
        int a = id >> 5, w = id & 31;
        float4 v = *(const float4*)(Arows + anch[tBase + a] * DIM + 4 * w);
        sA[a][w] = pack4(quants(v.x), quants(v.y), quants(v.z), quants(v.w));
    }
    if (tid < 32) {
        tau_s[tid] = g_tau[dir][tBase + tid];
        scnt[tid] = 0;
    }
    __syncthreads();

    // preload A fragments: [mtile][kstep][4]
    uint32_t afr[2][4][4];
    #pragma unroll
    for (int mt = 0; mt < 2; ++mt)
        #pragma unroll
        for (int ks = 0; ks < 4; ++ks) {
            afr[mt][ks][0] = sA[mt * 16 + gid][ks * 8 + tig];
            afr[mt][ks][1] = sA[mt * 16 + gid + 8][ks * 8 + tig];
            afr[mt][ks][2] = sA[mt * 16 + gid][ks * 8 + tig + 4];
            afr[mt][ks][3] = sA[mt * 16 + gid + 8][ks * 8 + tig + 4];
        }
    const int tau0 = tau_s[gid];
    const int tau1 = tau_s[gid + 8];
    const int tau2 = tau_s[16 + gid];
    const int tau3 = tau_s[16 + gid + 8];

    // tile loader: 128 rows x 128B -> padded smem (144B stride)
    auto load_tile = [&](int s, int t) {
        uint32_t sb = (uint32_t)__cvta_generic_to_shared(&sB[s][0][0]);
        const int n0 = segStart + t * TILE_N;
        #pragma unroll
        for (int i = 0; i < 4; ++i) {
            int id = tid + 256 * i;          // 1024 chunks of 16B
            int row = id >> 3;
            int cw = id & 7;
            const void* gp = (const char*)&g_Qrow[bsel][n0 + row][0] + cw * 16;
            cp_async16(sb + (uint32_t)(row * (BPAD * 4) + cw * 16), gp);
        }
        cp_commit();
    };

    load_tile(0, 0);

    for (int t = 0; t < TILES_PER_SEG; ++t) {
        if (t + 1 < TILES_PER_SEG) {
            load_tile((t + 1) & 1, t + 1);
            cp_wait<1>();
        } else {
            cp_wait<0>();
        }
        __syncthreads();

        const uint32_t (*B)[BPAD] = sB[t & 1];
        const int n0 = segStart + t * TILE_N;
        const int nw = warpId * 16;

        #pragma unroll
        for (int nt = 0; nt < 2; ++nt) {
            const int nb = nw + nt * 8;
            int c0[4] = {0, 0, 0, 0};
            int c1[4] = {0, 0, 0, 0};
            #pragma unroll
            for (int ks = 0; ks < 4; ++ks) {
                uint32_t b0 = B[nb + gid][ks * 8 + tig];
                uint32_t b1 = B[nb + gid][ks * 8 + tig + 4];
                mma_s8(c0, afr[0][ks], b0, b1);
                mma_s8(c1, afr[1][ks], b0, b1);
            }
            const int ncol = n0 + nb + tig * 2;
            int2 s2 = *(const int2*)&g_sumb2[bsel][ncol];
            // keys and threshold appends (rare)
            int k00 = s2.x - 2 * c0[0];   // anchor gid,     cand ncol
            int k01 = s2.y - 2 * c0[1];   // anchor gid,     cand ncol+1
            int k02 = s2.x - 2 * c0[2];   // anchor gid+8,   cand ncol
            int k03 = s2.y - 2 * c0[3];   // anchor gid+8,   cand ncol+1
            int k10 = s2.x - 2 * c1[0];   // anchor 16+gid
            int k11 = s2.y - 2 * c1[1];
            int k12 = s2.x - 2 * c1[2];   // anchor 24+gid
            int k13 = s2.y - 2 * c1[3];
            if (k00 < tau0) { int p = atomicAdd(&scnt[gid], 1);      if (p < PCAP) g_pool[dir][tBase + gid][seg][p] = ncol; }
            if (k01 < tau0) { int p = atomicAdd(&scnt[gid], 1);      if (p < PCAP) g_pool[dir][tBase + gid][seg][p] = ncol + 1; }
            if (k02 < tau1) { int p = atomicAdd(&scnt[gid + 8], 1);  if (p < PCAP) g_pool[dir][tBase + gid + 8][seg][p] = ncol; }
            if (k03 < tau1) { int p = atomicAdd(&scnt[gid + 8], 1);  if (p < PCAP) g_pool[dir][tBase + gid + 8][seg][p] = ncol + 1; }
            if (k10 < tau2) { int p = atomicAdd(&scnt[16 + gid], 1); if (p < PCAP) g_pool[dir][tBase + 16 + gid][seg][p] = ncol; }
            if (k11 < tau2) { int p = atomicAdd(&scnt[16 + gid], 1); if (p < PCAP) g_pool[dir][tBase + 16 + gid][seg][p] = ncol + 1; }
            if (k12 < tau3) { int p = atomicAdd(&scnt[24 + gid], 1); if (p < PCAP) g_pool[dir][tBase + 24 + gid][seg][p] = ncol; }
            if (k13 < tau3) { int p = atomicAdd(&scnt[24 + gid], 1); if (p < PCAP) g_pool[dir][tBase + 24 + gid][seg][p] = ncol + 1; }
        }
        __syncthreads();
    }

    if (tid < 32)
        g_cnt[dir][tBase + tid][seg] = min(scnt[tid], PCAP);
}

// ---------------- kernel 4: per-segment exact fp32 L1 top-10 (subwarp-coalesced) ----------------
__global__ __launch_bounds__(256)
void refine_seg_kernel(const float* __restrict__ out1, const float* __restrict__ out2,
                       const int* __restrict__ anchor1, const int* __restrict__ anchor2) {
    __shared__ float s_anc[8][DIM];
    const int warpId = threadIdx.x >> 5;
    const int lane = threadIdx.x & 31;
    const int sw = lane >> 3;
    const int sl = lane & 7;
    const int gid = blockIdx.x * 8 + warpId;      // 16384 warps
    const int seg = gid & 7;
    const int tt = (gid >> 3) & 1023;
    const int dir = gid >> 13;

    const float* Arows = (dir == 0) ? out1 : out2;
    const int* anch = (dir == 0) ? anchor1 : anchor2;
    const float* G = (dir == 0) ? out2 : out1;

    {
        const float4* src = (const float4*)(Arows + anch[tt] * DIM);
        ((float4*)&s_anc[warpId][0])[lane] = src[lane];
    }
    __syncwarp();
    const float4* anc4 = (const float4*)&s_anc[warpId][0];

    float kd[KNEG]; int ki[KNEG];
    #pragma unroll
    for (int k = 0; k < KNEG; ++k) { kd[k] = 3.0e38f; ki[k] = 0x7fffffff; }

    const int cnt = g_cnt[dir][tt][seg];
    const int* pool = &g_pool[dir][tt][seg][0];
    for (int base = 0; base < cnt; base += 4) {
        const int k = base + sw;
        int idx = -1;
        float dsum = 3.0e38f;
        if (k < cnt) {
            idx = min(pool[k], NPTS - 1);
            const float4* nr = (const float4*)(G + idx * DIM);
            float p = 0.0f;
            #pragma unroll
            for (int j = 0; j < 4; ++j) {
                float4 b = nr[sl + 8 * j];
                float4 a = anc4[sl + 8 * j];
                p += fabsf(a.x - b.x) + fabsf(a.y - b.y) +
                     fabsf(a.z - b.z) + fabsf(a.w - b.w);
            }
            p += __shfl_xor_sync(0xffffffffu, p, 4);
            p += __shfl_xor_sync(0xffffffffu, p, 2);
            p += __shfl_xor_sync(0xffffffffu, p, 1);
            dsum = p;
        } else {
            float p = 0.0f;
            p += __shfl_xor_sync(0xffffffffu, p, 4);
            p += __shfl_xor_sync(0xffffffffu, p, 2);
            p += __shfl_xor_sync(0xffffffffu, p, 1);
        }
        float thr = __shfl_sync(0xffffffffu, kd[KNEG - 1], 0);
        int   thi = __shfl_sync(0xffffffffu, ki[KNEG - 1], 0);
        bool candp = (sl == 0) && (idx >= 0) &&
                     (dsum < thr || (dsum == thr && idx < thi));
        unsigned m = __ballot_sync(0xffffffffu, candp);
        while (m) {
            int src = __ffs(m) - 1; m &= m - 1;
            float d = __shfl_sync(0xffffffffu, dsum, src);
            int  ix = __shfl_sync(0xffffffffu, idx, src);
            if (lane == 0) {
                bool better = (d < kd[KNEG - 1]) ||
                              (d == kd[KNEG - 1] && ix < ki[KNEG - 1]);
                if (better) {
                    int pos = KNEG - 1;
                    #pragma unroll
                    for (int q = KNEG - 2; q >= 0; --q)
                        if (kd[q] > d || (kd[q] == d && ki[q] > ix)) pos = q;
                    #pragma unroll
                    for (int q = KNEG - 1; q > 0; --q)
                        if (q > pos) { kd[q] = kd[q - 1]; ki[q] = ki[q - 1]; }
                    kd[pos] = d; ki[pos] = ix;
                }
            }
        }
    }
    if (lane == 0) {
        #pragma unroll
        for (int k = 0; k < KNEG; ++k) {
            g_segd[dir][tt][seg][k] = kd[k];
            g_segi[dir][tt][seg][k] = ki[k];
        }
    }
}

// ---------------- kernel 5: merge segments + loss ----------------
__global__ __launch_bounds__(256)
void merge_loss_kernel(const float* __restrict__ out1, const float* __restrict__ out2,
                       const int* __restrict__ anchor1, const int* __restrict__ anchor2) {
    const int warpId = threadIdx.x >> 5;
    const int lane = threadIdx.x & 31;
    const int g = blockIdx.x * 8 + warpId;
    const int dir = g >> 10;
    const int tt = g & 1023;

    const float* r1 = out1 + anchor1[tt] * DIM;
    const float* r2 = out2 + anchor2[tt] * DIM;
    float A = 0.0f;
    #pragma unroll
    for (int j = 0; j < 4; ++j)
        A += fabsf(r1[lane + 32 * j] - r2[lane + 32 * j]);
    A = warp_sum(A);
    const float Dm = A + GAMMA;

    if (lane == 0) {
        float kd[KNEG]; int ki[KNEG];
        #pragma unroll
        for (int k = 0; k < KNEG; ++k) { kd[k] = 3.0e38f; ki[k] = 0x7fffffff; }
        for (int seg = 0; seg < NSEG; ++seg) {
            #pragma unroll
            for (int k = 0; k < KNEG; ++k) {
                float d = g_segd[dir][tt][seg][k];
                int  ix = g_segi[dir][tt][seg][k];
                bool better = (d < kd[KNEG - 1]) ||
                              (d == kd[KNEG - 1] && ix < ki[KNEG - 1]);
                if (better) {
                    int pos = KNEG - 1;
                    #pragma unroll
                    for (int q = KNEG - 2; q >= 0; --q)
                        if (kd[q] > d || (kd[q] == d && ki[q] > ix)) pos = q;
                    #pragma unroll
                    for (int q = KNEG - 1; q > 0; --q)
                        if (q > pos) { kd[q] = kd[q - 1]; ki[q] = ki[q - 1]; }
                    kd[pos] = d; ki[pos] = ix;
                }
            }
        }
        float lsum = 0.0f;
        #pragma unroll
        for (int k = 0; k < KNEG; ++k) lsum += fmaxf(Dm - kd[k], 0.0f);
        g_partial[g] = lsum;
    }
}

// ---------------- kernel 6: deterministic reduction ----------------
__global__ void reduce_kernel(float* __restrict__ out) {
    __shared__ float sh[1024];
    int t = threadIdx.x;
    sh[t] = g_partial[t] + g_partial[t + 1024];
    __syncthreads();
    #pragma unroll
    for (int s = 512; s > 0; s >>= 1) {
        if (t < s) sh[t] += sh[t + s];
        __syncthreads();
    }
    if (t == 0) out[0] = sh[0] * (1.0f / (float)(TANCH * KNEG));
}

// ---------------- launch ----------------
extern "C" void kernel_launch(void* const* d_in, const int* in_sizes, int n_in,
                              void* d_out, int out_size) {
    const float* out1 = (const float*)d_in[0];
    const float* out2 = (const float*)d_in[1];
    const int* anchor1 = (const int*)d_in[2];
    const int* anchor2 = (const int*)d_in[3];
    float* out = (float*)d_out;

    quant_kernel<<<dim3(N_PAD / 64, 1, 2), 256>>>(out1, out2);

    tau_kernel<<<2 * TANCH / 8, 256>>>(out1, out2, anchor1, anchor2);

    mine_mma_kernel<<<dim3(TANCH / 32, NSEG, 2), 256>>>(out1, out2, anchor1, anchor2);

    refine_seg_kernel<<<2 * TANCH * NSEG / 8, 256>>>(out1, out2, anchor1, anchor2);

    merge_loss_kernel<<<2 * TANCH / 8, 256>>>(out1, out2, anchor1, anchor2);

    reduce_kernel<<<1, 1024>>>(out);
}